// round 1
// baseline (speedup 1.0000x reference)
#include <cuda_runtime.h>
#include <math.h>

#define Bdim 64
#define Sdim 256
#define Idim 128
#define Hdim 128
#define UNF  6
#define EPSV 1e-8f

// ---------------- device scratch (no allocations allowed) ----------------
__device__ float2 g_RecP[Hdim*Hdim];   // (0.5*sigma, 0.5*sigma*mu)  [src][dst]
__device__ float  g_RecW[Hdim*Hdim];   // 0.5*softplus(w)*erev       [src][dst]
__device__ float2 g_SenP[Idim*Hdim];   // (0.5*ss*iw, 0.5*ss*(smu-ib))
__device__ float  g_SenW[Idim*Hdim];   // 0.5*softplus(s_w)*s_erev
__device__ float  g_PhT[Hdim*Hdim];    // phase_W transposed: [k][d] = phase_W[d][k]
__device__ float  g_SaT[Hdim*Hdim];    // sa_W transposed
__device__ float  g_KN[Hdim];          // gl*vleak + Cn_rec + Cn_sen
__device__ float  g_KD[Hdim];          // cm_t + gl + Cd_rec + Cd_sen + eps
__device__ float  g_CmT[Hdim];         // softplus(cm)*UNFOLDS/DT

__device__ __forceinline__ float softplusf(float x) {
    return fmaxf(x, 0.f) + log1pf(expf(-fabsf(x)));
}
__device__ __forceinline__ float tanh_fast(float x) {
    float y; asm("tanh.approx.f32 %0, %1;" : "=f"(y) : "f"(x)); return y;
}

// ---------------- precompute: fold constants once per launch ----------------
__global__ void ltc_pre1(const float* __restrict__ sigma, const float* __restrict__ mu,
                         const float* __restrict__ w,     const float* __restrict__ erev,
                         const float* __restrict__ s_sigma, const float* __restrict__ s_mu,
                         const float* __restrict__ s_w,   const float* __restrict__ s_erev,
                         const float* __restrict__ input_w, const float* __restrict__ input_b,
                         const float* __restrict__ phase_W, const float* __restrict__ sa_W)
{
    int e = blockIdx.x * blockDim.x + threadIdx.x;
    if (e >= Hdim * Hdim) return;
    int src = e >> 7, d = e & 127;

    float sg = sigma[e];
    g_RecP[e] = make_float2(0.5f * sg, 0.5f * sg * mu[e]);
    g_RecW[e] = 0.5f * softplusf(w[e]) * erev[e];

    float ss = s_sigma[e];
    g_SenP[e] = make_float2(0.5f * ss * input_w[src],
                            0.5f * ss * (s_mu[e] - input_b[src]));
    g_SenW[e] = 0.5f * softplusf(s_w[e]) * s_erev[e];

    g_PhT[e] = phase_W[d * Hdim + src];
    g_SaT[e] = sa_W[d * Hdim + src];
}

__global__ void ltc_pre2(const float* __restrict__ gleak, const float* __restrict__ vleak,
                         const float* __restrict__ cm)
{
    int d = threadIdx.x;
    if (d >= Hdim) return;
    float Cn = 0.f, Cd = 0.f;
    for (int s = 0; s < Hdim; ++s) { float v = g_RecW[s * Hdim + d]; Cn += v; Cd += fabsf(v); }
    for (int i = 0; i < Idim; ++i) { float v = g_SenW[i * Hdim + d]; Cn += v; Cd += fabsf(v); }
    float gl  = softplusf(gleak[d]);
    float cmt = softplusf(cm[d]) * ((float)UNF / 1.0f);
    g_KN[d]  = gl * vleak[d] + Cn;
    g_KD[d]  = cmt + gl + Cd + EPSV;
    g_CmT[d] = cmt;
}

// ---------------- main persistent scan kernel: 1 CTA per batch ----------------
// smem layout (bytes):
//   [0,131072)        float2 sP[16384]
//   [131072,196608)   float  sW[16384]
//   [196608,...)      sv[128], sx[128], sg[128], red[512]
#define SMEM_BYTES (196608 + 3*512 + 2048)

__global__ __launch_bounds__(256, 1)
void ltc_main(const float* __restrict__ x, const float* __restrict__ h0,
              const float* __restrict__ amplitude, const float* __restrict__ omega,
              const float* __restrict__ phase_b,
              const float* __restrict__ alpha_p, const float* __restrict__ beta_p,
              float* __restrict__ out)
{
    extern __shared__ char smem[];
    float2* sP  = (float2*)smem;
    float*  sW  = (float*)(smem + 131072);
    float*  sv  = (float*)(smem + 196608);
    float*  sx  = sv + 128;
    float*  sg  = sx + 128;
    float*  red = sg + 128;   // 512 floats

    const int tid  = threadIdx.x;
    const int d    = tid & 127;
    const int half = tid >> 7;
    const int b    = blockIdx.x;
    const int s0   = half * 64;

    // cooperative load of recurrent matrices into smem (vectorized)
    {
        const float4* srcP = (const float4*)g_RecP;
        float4* dstP = (float4*)sP;
        #pragma unroll 4
        for (int i = tid; i < (Hdim*Hdim*2)/4; i += 256) dstP[i] = srcP[i];
        const float4* srcW = (const float4*)g_RecW;
        float4* dstW = (float4*)sW;
        #pragma unroll 4
        for (int i = tid; i < (Hdim*Hdim)/4; i += 256) dstW[i] = srcW[i];
    }

    const float alpha = *alpha_p;
    const float beta  = *beta_p;
    float KN = 0.f, KD = 0.f, cmt = 0.f, amp = 0.f, omg = 0.f, phb = 0.f, v = 0.f;
    if (half == 0) {
        KN  = g_KN[d];  KD = g_KD[d];  cmt = g_CmT[d];
        amp = amplitude[d]; omg = omega[d]; phb = phase_b[d];
        v   = h0[b * Hdim + d];
        sv[d] = v;
    }
    __syncthreads();

    for (int t = 0; t < Sdim; ++t) {
        // ---- load x_t ----
        if (half == 0) sx[d] = x[((b * Sdim) + t) * Idim + d];
        __syncthreads();

        // ---- sensory synapses (once per step), split over src halves ----
        float pn = 0.f, pd = 0.f;
        #pragma unroll 8
        for (int i = 0; i < 64; ++i) {
            int e = (s0 + i) * Hdim + d;
            float2 p = g_SenP[e];
            float ws = g_SenW[e];
            float arg = fmaf(p.x, sx[s0 + i], -p.y);
            float th  = tanh_fast(arg);
            pn = fmaf(ws, th, pn);
            pd = fmaf(fabsf(ws), th, pd);
        }
        red[half * 128 + d] = pn;
        red[256 + half * 128 + d] = pd;
        __syncthreads();

        float N0 = 0.f, D0 = 0.f;
        if (half == 0) {
            N0 = KN + red[d] + red[128 + d];
            D0 = KD + red[256 + d] + red[384 + d];
        }

        // ---- 6 semi-implicit ODE unfolds ----
        #pragma unroll 1
        for (int u = 0; u < UNF; ++u) {
            __syncthreads();   // sv (and red reuse) ready
            float qn = 0.f, qd = 0.f;
            #pragma unroll 8
            for (int i = 0; i < 64; ++i) {
                int e = (s0 + i) * Hdim + d;
                float2 p = sP[e];
                float ws = sW[e];
                float arg = fmaf(p.x, sv[s0 + i], -p.y);
                float th  = tanh_fast(arg);
                qn = fmaf(ws, th, qn);
                qd = fmaf(fabsf(ws), th, qd);
            }
            red[half * 128 + d] = qn;
            red[256 + half * 128 + d] = qd;
            __syncthreads();
            if (half == 0) {
                float num = fmaf(cmt, v, N0 + red[d] + red[128 + d]);
                float den = D0 + red[256 + d] + red[384 + d];
                v = num / den;
                sv[d] = v;
            }
        }
        __syncthreads();

        // ---- pulse: phi = v @ phase_W.T + phase_b ----
        float ph = 0.f;
        #pragma unroll 8
        for (int k = 0; k < 64; ++k)
            ph = fmaf(g_PhT[(s0 + k) * Hdim + d], sv[s0 + k], ph);
        red[half * 128 + d] = ph;
        __syncthreads();
        if (half == 0) {
            float phi = red[d] + red[128 + d] + phb;
            v = fmaf(alpha * amp, sinf(fmaf(omg, (float)t, phi)), v);
            sv[d] = v;
            sg[d] = 1.f / (1.f + __expf(-v));
        }
        __syncthreads();

        // ---- self-attend: v += beta * (sigmoid(v) @ sa_W.T) ----
        float sa = 0.f;
        #pragma unroll 8
        for (int k = 0; k < 64; ++k)
            sa = fmaf(g_SaT[(s0 + k) * Hdim + d], sg[s0 + k], sa);
        red[half * 128 + d] = sa;
        __syncthreads();
        if (half == 0) {
            v = fmaf(beta, red[d] + red[128 + d], v);
            sv[d] = v;
            out[((b * Sdim) + t) * Hdim + d] = v;
        }
        // next iteration's first __syncthreads orders red/sx reuse
    }

    if (half == 0) out[Bdim * Sdim * Hdim + b * Hdim + d] = v;
}

// ---------------- launch ----------------
extern "C" void kernel_launch(void* const* d_in, const int* in_sizes, int n_in,
                              void* d_out, int out_size)
{
    const float* x        = (const float*)d_in[0];
    const float* h0       = (const float*)d_in[1];
    const float* input_w  = (const float*)d_in[2];
    const float* input_b  = (const float*)d_in[3];
    const float* gleak    = (const float*)d_in[4];
    const float* vleak    = (const float*)d_in[5];
    const float* cm       = (const float*)d_in[6];
    const float* sigma    = (const float*)d_in[7];
    const float* mu       = (const float*)d_in[8];
    const float* w        = (const float*)d_in[9];
    const float* erev     = (const float*)d_in[10];
    const float* s_sigma  = (const float*)d_in[11];
    const float* s_mu     = (const float*)d_in[12];
    const float* s_w      = (const float*)d_in[13];
    const float* s_erev   = (const float*)d_in[14];
    const float* amplitude= (const float*)d_in[15];
    const float* omega    = (const float*)d_in[16];
    const float* phase_W  = (const float*)d_in[17];
    const float* phase_b  = (const float*)d_in[18];
    const float* alpha    = (const float*)d_in[19];
    const float* sa_W     = (const float*)d_in[20];
    const float* beta     = (const float*)d_in[21];
    float* out = (float*)d_out;

    ltc_pre1<<<64, 256>>>(sigma, mu, w, erev, s_sigma, s_mu, s_w, s_erev,
                          input_w, input_b, phase_W, sa_W);
    ltc_pre2<<<1, 128>>>(gleak, vleak, cm);

    cudaFuncSetAttribute(ltc_main, cudaFuncAttributeMaxDynamicSharedMemorySize, SMEM_BYTES);
    ltc_main<<<Bdim, 256, SMEM_BYTES>>>(x, h0, amplitude, omega, phase_b,
                                        alpha, beta, out);
}

// round 2
// speedup vs baseline: 1.9499x; 1.9499x over previous
#include <cuda_runtime.h>
#include <cuda_fp16.h>
#include <math.h>
#include <stdint.h>

#define Bdim 64
#define Sdim 256
#define Idim 128
#define Hdim 128
#define UNF  6
#define EPSV 1e-8f

// ---------------- device scratch ----------------
__device__ float2 g_RecP[Hdim*Hdim];   // (0.5*sigma, 0.5*sigma*mu)  [src][dst]
__device__ float  g_RecW[Hdim*Hdim];   // 0.5*softplus(w)*erev       [src][dst]
__device__ float2 g_SenP[Idim*Hdim];   // (0.5*ss*iw, 0.5*ss*(smu-ib))
__device__ float  g_SenW[Idim*Hdim];   // 0.5*softplus(s_w)*s_erev
__device__ __half g_PhTh[Hdim*Hdim];   // phase_W transposed fp16: [k][d]
__device__ __half g_SaTh[Hdim*Hdim];   // sa_W transposed fp16
__device__ float  g_KN[Hdim];
__device__ float  g_KD[Hdim];
__device__ float  g_CmT[Hdim];
__device__ float2 g_Sen[Bdim*Sdim*Hdim];  // per-(b,t,d): (w_num_s_tanh, w_den_s_tanh)

__device__ __forceinline__ float softplusf(float x) {
    return fmaxf(x, 0.f) + log1pf(expf(-fabsf(x)));
}
__device__ __forceinline__ float tanh_fast(float x) {
    float y; asm("tanh.approx.f32 %0, %1;" : "=f"(y) : "f"(x)); return y;
}
__device__ __forceinline__ uint32_t smem_u32(const void* p) {
    uint32_t a;
    asm("{ .reg .u64 t; cvta.to.shared.u64 t, %1; cvt.u32.u64 %0, t; }" : "=r"(a) : "l"(p));
    return a;
}
__device__ __forceinline__ uint32_t ctarank() {
    uint32_t r; asm("mov.u32 %0, %%cluster_ctarank;" : "=r"(r)); return r;
}
__device__ __forceinline__ void st_remote_f32(uint32_t saddr, uint32_t peer, float v) {
    asm volatile(
        "{\n\t.reg .b32 r;\n\t"
        "mapa.shared::cluster.u32 r, %0, %1;\n\t"
        "st.shared::cluster.f32 [r], %2;\n\t}"
        :: "r"(saddr), "r"(peer), "f"(v) : "memory");
}
__device__ __forceinline__ void mbar_arrive_remote(uint32_t mbar, uint32_t peer) {
    asm volatile(
        "{\n\t.reg .b32 r;\n\t"
        "mapa.shared::cluster.u32 r, %0, %1;\n\t"
        "mbarrier.arrive.release.cluster.shared::cluster.b64 _, [r];\n\t}"
        :: "r"(mbar), "r"(peer) : "memory");
}
__device__ __forceinline__ void mbar_wait_par(uint32_t mbar, uint32_t parity) {
    asm volatile(
        "{\n\t.reg .pred P1;\n\t"
        "WAITL_%=:\n\t"
        "mbarrier.try_wait.parity.acquire.cluster.shared::cta.b64 P1, [%0], %1, 0x989680;\n\t"
        "@P1 bra.uni DONEL_%=;\n\t"
        "bra.uni WAITL_%=;\n\t"
        "DONEL_%=:\n\t}"
        :: "r"(mbar), "r"(parity) : "memory");
}

// ---------------- precompute ----------------
__global__ void ltc_pre1(const float* __restrict__ sigma, const float* __restrict__ mu,
                         const float* __restrict__ w,     const float* __restrict__ erev,
                         const float* __restrict__ s_sigma, const float* __restrict__ s_mu,
                         const float* __restrict__ s_w,   const float* __restrict__ s_erev,
                         const float* __restrict__ input_w, const float* __restrict__ input_b,
                         const float* __restrict__ phase_W, const float* __restrict__ sa_W)
{
    int e = blockIdx.x * blockDim.x + threadIdx.x;
    if (e >= Hdim * Hdim) return;
    int src = e >> 7, d = e & 127;

    float sg = sigma[e];
    g_RecP[e] = make_float2(0.5f * sg, 0.5f * sg * mu[e]);
    g_RecW[e] = 0.5f * softplusf(w[e]) * erev[e];

    float ss = s_sigma[e];
    g_SenP[e] = make_float2(0.5f * ss * input_w[src],
                            0.5f * ss * (s_mu[e] - input_b[src]));
    g_SenW[e] = 0.5f * softplusf(s_w[e]) * s_erev[e];

    g_PhTh[e] = __float2half(phase_W[d * Hdim + src]);
    g_SaTh[e] = __float2half(sa_W[d * Hdim + src]);
}

__global__ void ltc_pre2(const float* __restrict__ gleak, const float* __restrict__ vleak,
                         const float* __restrict__ cm)
{
    int d = threadIdx.x;
    if (d >= Hdim) return;
    float Cn = 0.f, Cd = 0.f;
    for (int s = 0; s < Hdim; ++s) { float v = g_RecW[s * Hdim + d]; Cn += v; Cd += fabsf(v); }
    for (int i = 0; i < Idim; ++i) { float v = g_SenW[i * Hdim + d]; Cn += v; Cd += fabsf(v); }
    float gl  = softplusf(gleak[d]);
    float cmt = softplusf(cm[d]) * ((float)UNF / 1.0f);
    g_KN[d]  = gl * vleak[d] + Cn;
    g_KD[d]  = cmt + gl + Cd + EPSV;
    g_CmT[d] = cmt;
}

// ---------------- sensory precompute: fully parallel over (b,t) ----------------
// smem: pP float2[16384] @0 (131072), pW float[16384] @131072 (65536),
//       sx[128] @196608 (512), red[512] @197120 (2048)  -> 199168
#define SEN_SMEM 199168

__global__ __launch_bounds__(256, 1)
void ltc_sensory(const float* __restrict__ x)
{
    extern __shared__ char smem[];
    float2* pP = (float2*)smem;
    float*  pW = (float*)(smem + 131072);
    float*  sx = (float*)(smem + 196608);
    float*  red= (float*)(smem + 197120);

    const int tid = threadIdx.x;
    // cache sensory params
    {
        const float4* s4 = (const float4*)g_SenP;
        float4* d4 = (float4*)pP;
        #pragma unroll 4
        for (int i = tid; i < (Idim*Hdim*2)/4; i += 256) d4[i] = s4[i];
        const float4* w4 = (const float4*)g_SenW;
        float4* dw = (float4*)pW;
        #pragma unroll 4
        for (int i = tid; i < (Idim*Hdim)/4; i += 256) dw[i] = w4[i];
    }
    __syncthreads();

    const int d  = tid & 127;
    const int s0 = (tid >> 7) * 64;

    for (int item = blockIdx.x; item < Bdim*Sdim; item += gridDim.x) {
        if (tid < 128) sx[tid] = x[item * Idim + tid];
        __syncthreads();
        float qn = 0.f, qd = 0.f;
        #pragma unroll 8
        for (int i = 0; i < 64; ++i) {
            int e = (s0 + i) * Hdim + d;
            float2 p = pP[e];
            float ws = pW[e];
            float th = tanh_fast(fmaf(p.x, sx[s0 + i], -p.y));
            qn = fmaf(ws, th, qn);
            qd = fmaf(fabsf(ws), th, qd);
        }
        red[tid] = qn;
        red[256 + tid] = qd;
        __syncthreads();
        if (tid < 128)
            g_Sen[item * Hdim + tid] = make_float2(red[tid] + red[tid + 128],
                                                   red[256 + tid] + red[384 + tid]);
        __syncthreads();
    }
}

// ---------------- scan kernel: cluster of 2 CTAs per batch, dst-split ----------------
// smem layout:
//   0       sP   float2[128*64]  65536
//   65536   sW   float [128*64]  32768  -> 98304
//   98304   sPh  half  [128*128] 32768  -> 131072
//   131072  sSa  half  [128*128] 32768  -> 163840
//   163840  sv0  float[128]      512
//   164352  sv1  float[128]      512
//   164864  sg   float[128]      512
//   165376  red  float[512]      2048   -> 167424
//   167424  mbar u64             8
#define SCAN_SMEM 167936

__global__ __launch_bounds__(256, 1) __cluster_dims__(2, 1, 1)
void ltc_scan(const float* __restrict__ x, const float* __restrict__ h0,
              const float* __restrict__ amplitude, const float* __restrict__ omega,
              const float* __restrict__ phase_b,
              const float* __restrict__ alpha_p, const float* __restrict__ beta_p,
              float* __restrict__ out)
{
    extern __shared__ char smem[];
    float2* sP  = (float2*)smem;
    float*  sW  = (float*)(smem + 65536);
    __half* sPh = (__half*)(smem + 98304);
    __half* sSa = (__half*)(smem + 131072);
    float*  sv0 = (float*)(smem + 163840);
    float*  sv1 = (float*)(smem + 164352);
    float*  sg  = (float*)(smem + 164864);
    float*  red = (float*)(smem + 165376);

    const int tid   = threadIdx.x;
    const uint32_t rank = ctarank();
    const uint32_t peer = rank ^ 1u;
    const int b = blockIdx.x >> 1;

    const uint32_t sv0_a  = smem_u32(sv0);
    const uint32_t sv1_a  = smem_u32(sv1);
    const uint32_t mbar_a = smem_u32(smem + 167424);

    // load recurrent slice [128 src][64 own dst]
    for (int i = tid; i < Hdim * 64; i += 256) {
        int src = i >> 6, dl = i & 63;
        sP[i] = g_RecP[src * Hdim + rank * 64 + dl];
        sW[i] = g_RecW[src * Hdim + rank * 64 + dl];
    }
    // full fp16 matvec weights
    {
        const float4* ph4 = (const float4*)g_PhTh;   // 8 halfs per float4
        float4* dph = (float4*)sPh;
        #pragma unroll 4
        for (int i = tid; i < (Hdim*Hdim)/8; i += 256) dph[i] = ph4[i];
        const float4* sa4 = (const float4*)g_SaTh;
        float4* dsa = (float4*)sSa;
        #pragma unroll 4
        for (int i = tid; i < (Hdim*Hdim)/8; i += 256) dsa[i] = sa4[i];
    }
    if (tid < 128) sv0[tid] = h0[b * Hdim + tid];
    if (tid == 0) {
        asm volatile("mbarrier.init.shared.b64 [%0], 64;" :: "r"(mbar_a) : "memory");
    }
    __syncthreads();
    asm volatile("barrier.cluster.arrive.aligned;" ::: "memory");
    asm volatile("barrier.cluster.wait.aligned;" ::: "memory");

    const float alpha = *alpha_p;
    const float beta  = *beta_p;

    // per-dst constants for unfold writers (tid < 64)
    const int dOwn = rank * 64 + (tid & 63);
    float KN = 0.f, KD = 0.f, cmt = 0.f;
    if (tid < 64) { KN = g_KN[dOwn]; KD = g_KD[dOwn]; cmt = g_CmT[dOwn]; }
    // per-dst constants for epilogue (tid < 128)
    float aamp = 0.f, omg = 0.f, phb = 0.f;
    if (tid < 128) { aamp = alpha * amplitude[tid]; omg = omega[tid]; phb = phase_b[tid]; }

    const int g  = tid >> 6;        // src group 0..3
    const int dl = tid & 63;
    const int s0 = g * 32;
    const int d2 = tid & 127;       // epilogue dst
    const int k0 = (tid >> 7) * 64; // epilogue k group

    uint32_t phase = 0;

    for (int t = 0; t < Sdim; ++t) {
        float2 sen = make_float2(0.f, 0.f);
        if (tid < 64) sen = g_Sen[(size_t)(b * Sdim + t) * Hdim + dOwn];
        float N0 = KN + sen.x;
        float D0 = KD + sen.y;

        float* svR = sv0; float* svW = sv1;
        uint32_t svWa = sv1_a;

        #pragma unroll 1
        for (int u = 0; u < UNF; ++u) {
            float qn = 0.f, qd = 0.f;
            #pragma unroll
            for (int i = 0; i < 32; ++i) {
                float vs = svR[s0 + i];
                float2 p = sP[(s0 + i) * 64 + dl];
                float ws = sW[(s0 + i) * 64 + dl];
                float th = tanh_fast(fmaf(p.x, vs, -p.y));
                qn = fmaf(ws, th, qn);
                qd = fmaf(fabsf(ws), th, qd);
            }
            red[tid] = qn;
            red[256 + tid] = qd;
            __syncthreads();
            if (tid < 64) {
                float num = N0 + red[tid] + red[tid + 64] + red[tid + 128] + red[tid + 192];
                float den = D0 + red[tid + 256] + red[tid + 320] + red[tid + 384] + red[tid + 448];
                float vnew = __fdividef(fmaf(cmt, svR[dOwn], num), den);
                svW[dOwn] = vnew;                        // local
                st_remote_f32(svWa + dOwn * 4, peer, vnew);  // peer
                mbar_arrive_remote(mbar_a, peer);            // release
            }
            __syncthreads();
            mbar_wait_par(mbar_a, phase);                    // acquire peer's 64 values
            phase ^= 1u;
            float* tp = svR; svR = svW; svW = tp;
            svWa = (svWa == sv1_a) ? sv0_a : sv1_a;
        }
        // after 6 unfolds, full v is in sv0 (both CTAs). Epilogue computed redundantly.

        // pulse: phi = v @ phase_W^T + phase_b
        {
            float ph = 0.f;
            #pragma unroll 16
            for (int k = 0; k < 64; ++k)
                ph = fmaf(__half2float(sPh[(k0 + k) * Hdim + d2]), sv0[k0 + k], ph);
            red[tid] = ph;
        }
        __syncthreads();
        if (tid < 128) {
            float phi = red[tid] + red[tid + 128] + phb;
            float vv = sv0[tid];
            vv = fmaf(aamp, sinf(fmaf(omg, (float)t, phi)), vv);
            sv0[tid] = vv;
            sg[tid] = 0.5f + 0.5f * tanh_fast(0.5f * vv);
        }
        __syncthreads();
        // self-attend: v += beta * (sigmoid(v) @ sa_W^T)
        {
            float sa = 0.f;
            #pragma unroll 16
            for (int k = 0; k < 64; ++k)
                sa = fmaf(__half2float(sSa[(k0 + k) * Hdim + d2]), sg[k0 + k], sa);
            red[tid] = sa;
        }
        __syncthreads();
        if (tid < 128) {
            float vv = fmaf(beta, red[tid] + red[tid + 128], sv0[tid]);
            sv0[tid] = vv;
            if ((tid >> 6) == (int)rank)
                out[(size_t)(b * Sdim + t) * Hdim + tid] = vv;
        }
        __syncthreads();
    }

    if (tid < 128 && (tid >> 6) == (int)rank)
        out[(size_t)Bdim * Sdim * Hdim + b * Hdim + tid] = sv0[tid];
}

// ---------------- launch ----------------
extern "C" void kernel_launch(void* const* d_in, const int* in_sizes, int n_in,
                              void* d_out, int out_size)
{
    const float* x        = (const float*)d_in[0];
    const float* h0       = (const float*)d_in[1];
    const float* input_w  = (const float*)d_in[2];
    const float* input_b  = (const float*)d_in[3];
    const float* gleak    = (const float*)d_in[4];
    const float* vleak    = (const float*)d_in[5];
    const float* cm       = (const float*)d_in[6];
    const float* sigma    = (const float*)d_in[7];
    const float* mu       = (const float*)d_in[8];
    const float* w        = (const float*)d_in[9];
    const float* erev     = (const float*)d_in[10];
    const float* s_sigma  = (const float*)d_in[11];
    const float* s_mu     = (const float*)d_in[12];
    const float* s_w      = (const float*)d_in[13];
    const float* s_erev   = (const float*)d_in[14];
    const float* amplitude= (const float*)d_in[15];
    const float* omega    = (const float*)d_in[16];
    const float* phase_W  = (const float*)d_in[17];
    const float* phase_b  = (const float*)d_in[18];
    const float* alpha    = (const float*)d_in[19];
    const float* sa_W     = (const float*)d_in[20];
    const float* beta     = (const float*)d_in[21];
    float* out = (float*)d_out;

    ltc_pre1<<<64, 256>>>(sigma, mu, w, erev, s_sigma, s_mu, s_w, s_erev,
                          input_w, input_b, phase_W, sa_W);
    ltc_pre2<<<1, 128>>>(gleak, vleak, cm);

    cudaFuncSetAttribute(ltc_sensory, cudaFuncAttributeMaxDynamicSharedMemorySize, SEN_SMEM);
    ltc_sensory<<<148, 256, SEN_SMEM>>>(x);

    cudaFuncSetAttribute(ltc_scan, cudaFuncAttributeMaxDynamicSharedMemorySize, SCAN_SMEM);
    ltc_scan<<<Bdim * 2, 256, SCAN_SMEM>>>(x, h0, amplitude, omega, phase_b,
                                           alpha, beta, out);
}

// round 5
// speedup vs baseline: 1.9952x; 1.0232x over previous
#include <cuda_runtime.h>
#include <cuda_fp16.h>
#include <math.h>
#include <stdint.h>

#define Bdim 64
#define Sdim 256
#define Idim 128
#define Hdim 128
#define UNF  6
#define EPSV 1e-8f

// ---------------- device scratch ----------------
// pair-packed recurrent params: index e = p*128 + d, p = src/2
__device__ __half2 g_RP1[64*Hdim];   // (0.5*sigma[2p,d], 0.5*sigma[2p+1,d])
__device__ __half2 g_RC [64*Hdim];   // (-0.5*sigma*mu) pairs
__device__ __half2 g_RW [64*Hdim];   // (0.5*softplus(w)*erev) pairs
// pair-packed sensory params
__device__ __half2 g_SP1[64*Hdim];   // (0.5*ss*iw) pairs
__device__ __half2 g_SC [64*Hdim];   // (0.5*ss*(ib - s_mu)) pairs
__device__ __half2 g_SW [64*Hdim];   // (0.5*softplus(s_w)*s_erev) pairs
// epilogue matvec weights, [d][k] row-major fp16
__device__ __half  g_Ph[Hdim*Hdim];
__device__ __half  g_Sa[Hdim*Hdim];
__device__ float   g_KN[Hdim];
__device__ float   g_KD[Hdim];
__device__ float   g_CmT[Hdim];
__device__ float2  g_Sen[Bdim*Sdim*Hdim];   // per-(b,t,d): (num_s, den_s)

static __device__ __forceinline__ float ltc_softplus(float x) {
    return fmaxf(x, 0.f) + log1pf(expf(-fabsf(x)));
}
static __device__ __forceinline__ float ltc_tanh_f32(float x) {
    float y; asm("tanh.approx.f32 %0, %1;" : "=f"(y) : "f"(x)); return y;
}
static __device__ __forceinline__ __half2 ltc_tanh_h2(__half2 x) {
    uint32_t xi = *reinterpret_cast<uint32_t*>(&x);
    uint32_t yi;
    asm("tanh.approx.f16x2 %0, %1;" : "=r"(yi) : "r"(xi));
    return *reinterpret_cast<__half2*>(&yi);
}
static __device__ __forceinline__ uint32_t ltc_smem_u32(const void* p) {
    uint32_t a;
    asm("{ .reg .u64 t; cvta.to.shared.u64 t, %1; cvt.u32.u64 %0, t; }" : "=r"(a) : "l"(p));
    return a;
}
static __device__ __forceinline__ uint32_t ltc_ctarank() {
    uint32_t r; asm("mov.u32 %0, %%cluster_ctarank;" : "=r"(r)); return r;
}
static __device__ __forceinline__ void ltc_st_remote_f32(uint32_t saddr, uint32_t peer, float v) {
    asm volatile(
        "{\n\t.reg .b32 r;\n\t"
        "mapa.shared::cluster.u32 r, %0, %1;\n\t"
        "st.shared::cluster.f32 [r], %2;\n\t}"
        :: "r"(saddr), "r"(peer), "f"(v) : "memory");
}
static __device__ __forceinline__ void ltc_st_remote_u16(uint32_t saddr, uint32_t peer, unsigned short v) {
    asm volatile(
        "{\n\t.reg .b32 r;\n\t"
        "mapa.shared::cluster.u32 r, %0, %1;\n\t"
        "st.shared::cluster.u16 [r], %2;\n\t}"
        :: "r"(saddr), "r"(peer), "h"(v) : "memory");
}
static __device__ __forceinline__ void ltc_mbar_arrive_local(uint32_t mbar) {
    asm volatile("mbarrier.arrive.release.cluster.shared::cta.b64 _, [%0];"
                 :: "r"(mbar) : "memory");
}
static __device__ __forceinline__ void ltc_mbar_arrive_remote(uint32_t mbar, uint32_t peer) {
    asm volatile(
        "{\n\t.reg .b32 r;\n\t"
        "mapa.shared::cluster.u32 r, %0, %1;\n\t"
        "mbarrier.arrive.release.cluster.shared::cluster.b64 _, [r];\n\t}"
        :: "r"(mbar), "r"(peer) : "memory");
}
static __device__ __forceinline__ void ltc_mbar_wait_par(uint32_t mbar, uint32_t parity) {
    asm volatile(
        "{\n\t.reg .pred P1;\n\t"
        "WAITL_%=:\n\t"
        "mbarrier.try_wait.parity.acquire.cluster.shared::cta.b64 P1, [%0], %1, 0x989680;\n\t"
        "@P1 bra.uni DONEL_%=;\n\t"
        "bra.uni WAITL_%=;\n\t"
        "DONEL_%=:\n\t}"
        :: "r"(mbar), "r"(parity) : "memory");
}

// ---------------- precompute ----------------
__global__ void ltc_pre1(const float* __restrict__ sigma, const float* __restrict__ mu,
                         const float* __restrict__ w,     const float* __restrict__ erev,
                         const float* __restrict__ s_sigma, const float* __restrict__ s_mu,
                         const float* __restrict__ s_w,   const float* __restrict__ s_erev,
                         const float* __restrict__ input_w, const float* __restrict__ input_b,
                         const float* __restrict__ phase_W, const float* __restrict__ sa_W)
{
    int e = blockIdx.x * blockDim.x + threadIdx.x;
    if (e >= Hdim * Hdim) return;
    // epilogue weights: identity layout [d][k]
    g_Ph[e] = __float2half(phase_W[e]);
    g_Sa[e] = __float2half(sa_W[e]);

    if (e < 64 * Hdim) {
        int p = e >> 7, d = e & 127;
        int s0 = 2 * p, s1 = 2 * p + 1;
        float sg0 = sigma[s0*Hdim+d], sg1 = sigma[s1*Hdim+d];
        g_RP1[e] = __floats2half2_rn(0.5f*sg0, 0.5f*sg1);
        g_RC [e] = __floats2half2_rn(-0.5f*sg0*mu[s0*Hdim+d], -0.5f*sg1*mu[s1*Hdim+d]);
        g_RW [e] = __floats2half2_rn(0.5f*ltc_softplus(w[s0*Hdim+d])*erev[s0*Hdim+d],
                                     0.5f*ltc_softplus(w[s1*Hdim+d])*erev[s1*Hdim+d]);
        float ss0 = s_sigma[s0*Hdim+d], ss1 = s_sigma[s1*Hdim+d];
        g_SP1[e] = __floats2half2_rn(0.5f*ss0*input_w[s0], 0.5f*ss1*input_w[s1]);
        g_SC [e] = __floats2half2_rn(0.5f*ss0*(input_b[s0]-s_mu[s0*Hdim+d]),
                                     0.5f*ss1*(input_b[s1]-s_mu[s1*Hdim+d]));
        g_SW [e] = __floats2half2_rn(0.5f*ltc_softplus(s_w[s0*Hdim+d])*s_erev[s0*Hdim+d],
                                     0.5f*ltc_softplus(s_w[s1*Hdim+d])*s_erev[s1*Hdim+d]);
    }
}

__global__ void ltc_pre2(const float* __restrict__ gleak, const float* __restrict__ vleak,
                         const float* __restrict__ cm,
                         const float* __restrict__ w, const float* __restrict__ erev,
                         const float* __restrict__ s_w, const float* __restrict__ s_erev)
{
    int d = threadIdx.x;
    if (d >= Hdim) return;
    float Cn = 0.f, Cd = 0.f;
    for (int s = 0; s < Hdim; ++s) {
        float v = 0.5f * ltc_softplus(w[s*Hdim+d]) * erev[s*Hdim+d];
        Cn += v; Cd += fabsf(v);
    }
    for (int i = 0; i < Idim; ++i) {
        float v = 0.5f * ltc_softplus(s_w[i*Hdim+d]) * s_erev[i*Hdim+d];
        Cn += v; Cd += fabsf(v);
    }
    float gl  = ltc_softplus(gleak[d]);
    float cmt = ltc_softplus(cm[d]) * ((float)UNF / 1.0f);
    g_KN[d]  = gl * vleak[d] + Cn;
    g_KD[d]  = cmt + gl + Cd + EPSV;
    g_CmT[d] = cmt;
}

// ---------------- sensory precompute (parallel over all (b,t)) ----------------
// smem: sP1 32768 @0, sC 32768 @32768, sW 32768 @65536, sxh 256 @98304, red 2048 @98560
#define SEN_SMEM 100608

__global__ __launch_bounds__(256, 1)
void ltc_sensory(const float* __restrict__ x)
{
    extern __shared__ char smem[];
    __half2* sP1 = (__half2*)smem;
    __half2* sC  = (__half2*)(smem + 32768);
    __half2* sW  = (__half2*)(smem + 65536);
    __half2* sxh = (__half2*)(smem + 98304);
    float*   red = (float*)(smem + 98560);

    const int tid = threadIdx.x;
    for (int i = tid; i < 64*Hdim; i += 256) {
        sP1[i] = g_SP1[i]; sC[i] = g_SC[i]; sW[i] = g_SW[i];
    }
    __syncthreads();

    const int d  = tid & 127;
    const int p0 = (tid >> 7) * 32;

    for (int item = blockIdx.x; item < Bdim*Sdim; item += gridDim.x) {
        if (tid < 64) {
            float2 x2 = ((const float2*)(x + (size_t)item * Idim))[tid];
            sxh[tid] = __floats2half2_rn(x2.x, x2.y);
        }
        __syncthreads();
        float qn = 0.f, qd = 0.f;
        #pragma unroll
        for (int i = 0; i < 32; ++i) {
            int e = (p0 + i) * Hdim + d;
            __half2 arg = __hfma2(sP1[e], sxh[p0 + i], sC[e]);
            float2 th = __half22float2(ltc_tanh_h2(arg));
            float2 wf = __half22float2(sW[e]);
            qn = fmaf(wf.x, th.x, qn); qn = fmaf(wf.y, th.y, qn);
            qd = fmaf(fabsf(wf.x), th.x, qd); qd = fmaf(fabsf(wf.y), th.y, qd);
        }
        red[tid] = qn;
        red[256 + tid] = qd;
        __syncthreads();
        if (tid < 128)
            g_Sen[(size_t)item * Hdim + tid] = make_float2(red[tid] + red[tid + 128],
                                                           red[256 + tid] + red[384 + tid]);
        __syncthreads();
    }
}

// ---------------- scan kernel: 2-CTA cluster per batch, dst-split ----------------
// smem:
//   0       sP1  half2[64*64]    16384
//   16384   sC   half2[64*64]    16384
//   32768   sW   half2[64*64]    16384  -> 49152
//   49152   sPh  half [128 rows, pitch 130] 33280 -> 82432
//   82432   sSa  half [128 rows, pitch 130] 33280 -> 115712
//   115712  svh0 half[128]       256
//   115968  svh1 half[128]       256
//   116224  svF  float[128]      512
//   116736  sgs  float[128]      512
//   117248  red  float[512]      2048  -> 119296
//   119296  mbar u64             8
#define SCAN_SMEM 119424
#define PH_PITCH 130

__global__ __launch_bounds__(256, 1) __cluster_dims__(2, 1, 1)
void ltc_scan(const float* __restrict__ h0,
              const float* __restrict__ amplitude, const float* __restrict__ omega,
              const float* __restrict__ phase_b,
              const float* __restrict__ alpha_p, const float* __restrict__ beta_p,
              float* __restrict__ out)
{
    extern __shared__ char smem[];
    __half2* sP1 = (__half2*)smem;
    __half2* sC  = (__half2*)(smem + 16384);
    __half2* sW  = (__half2*)(smem + 32768);
    __half*  sPh = (__half*)(smem + 49152);
    __half*  sSa = (__half*)(smem + 82432);
    __half*  svh0= (__half*)(smem + 115712);
    __half*  svh1= (__half*)(smem + 115968);
    float*   svF = (float*)(smem + 116224);
    float*   sgs = (float*)(smem + 116736);
    float*   red = (float*)(smem + 117248);

    const int tid = threadIdx.x;
    const uint32_t rank = ltc_ctarank();
    const uint32_t peer = rank ^ 1u;
    const int b = blockIdx.x >> 1;

    const uint32_t svh0_a = ltc_smem_u32(svh0);
    const uint32_t svh1_a = ltc_smem_u32(svh1);
    const uint32_t svF_a  = ltc_smem_u32(svF);
    const uint32_t mbar_a = ltc_smem_u32(smem + 119296);

    // load own-dst recurrent slices: [p (64)][dl (64)]
    for (int i = tid; i < 64 * 64; i += 256) {
        int p = i >> 6, dl = i & 63;
        int e = p * Hdim + rank * 64 + dl;
        sP1[i] = g_RP1[e]; sC[i] = g_RC[e]; sW[i] = g_RW[e];
    }
    // epilogue weights into padded rows (pitch 130 halfs = 260 B)
    {
        const __half2* ph2 = (const __half2*)g_Ph;
        const __half2* sa2 = (const __half2*)g_Sa;
        #pragma unroll 4
        for (int i = tid; i < (Hdim*Hdim)/2; i += 256) {
            int dd = i >> 6, jj = i & 63;
            ((__half2*)((char*)sPh + dd * (PH_PITCH*2)))[jj] = ph2[i];
            ((__half2*)((char*)sSa + dd * (PH_PITCH*2)))[jj] = sa2[i];
        }
    }
    if (tid < 128) {
        float v = h0[b * Hdim + tid];
        svF[tid] = v;
        svh0[tid] = __float2half(v);
    }
    if (tid == 0)
        asm volatile("mbarrier.init.shared.b64 [%0], 128;" :: "r"(mbar_a) : "memory");
    __syncthreads();
    asm volatile("barrier.cluster.arrive.aligned;" ::: "memory");
    asm volatile("barrier.cluster.wait.aligned;" ::: "memory");

    const float alpha = *alpha_p;
    const float beta  = *beta_p;

    const int dOwn = rank * 64 + (tid & 63);   // writers (tid<64)
    float KN = 0.f, KD = 0.f, cmt = 0.f;
    if (tid < 64) { KN = g_KN[dOwn]; KD = g_KD[dOwn]; cmt = g_CmT[dOwn]; }
    float aamp = 0.f, omg = 0.f, phb = 0.f;
    if (tid < 128) { aamp = alpha * amplitude[tid]; omg = omega[tid]; phb = phase_b[tid]; }

    const int g  = tid >> 6;         // src-pair group 0..3
    const int dl = tid & 63;
    const int p0 = g * 16;
    const int d2 = tid & 127;        // epilogue dst
    const int k0 = (tid >> 7) * 64;  // epilogue k half

    uint32_t parity = 0;

    for (int t = 0; t < Sdim; ++t) {
        float N0 = 0.f, D0 = 0.f, vreg = 0.f;
        if (tid < 64) {
            float2 sen = g_Sen[(size_t)(b * Sdim + t) * Hdim + dOwn];
            N0 = KN + sen.x; D0 = KD + sen.y;
            vreg = svF[dOwn];
        }

        const __half* svR = svh0;
        __half* svW = svh1;
        uint32_t svWa = svh1_a;

        #pragma unroll 1
        for (int u = 0; u < UNF; ++u) {
            const __half2* svR2 = (const __half2*)svR;
            float qn = 0.f, qd = 0.f;
            #pragma unroll
            for (int i = 0; i < 16; ++i) {
                int e = (p0 + i) * 64 + dl;
                __half2 arg = __hfma2(sP1[e], svR2[p0 + i], sC[e]);
                float2 th = __half22float2(ltc_tanh_h2(arg));
                float2 wf = __half22float2(sW[e]);
                qn = fmaf(wf.x, th.x, qn); qn = fmaf(wf.y, th.y, qn);
                qd = fmaf(fabsf(wf.x), th.x, qd); qd = fmaf(fabsf(wf.y), th.y, qd);
            }
            red[tid] = qn;
            red[256 + tid] = qd;
            __syncthreads();
            if (tid < 64) {
                int wdl = tid;
                float num = N0 + red[wdl] + red[wdl+64] + red[wdl+128] + red[wdl+192];
                float den = D0 + red[256+wdl] + red[256+wdl+64] + red[256+wdl+128] + red[256+wdl+192];
                vreg = __fdividef(fmaf(cmt, vreg, num), den);
                __half vh = __float2half(vreg);
                svW[dOwn] = vh;                                              // local
                ltc_st_remote_u16(svWa + dOwn * 2, peer, __half_as_ushort(vh)); // peer
                if (u == UNF - 1) {
                    svF[dOwn] = vreg;
                    ltc_st_remote_f32(svF_a + dOwn * 4, peer, vreg);
                }
                ltc_mbar_arrive_local(mbar_a);
                ltc_mbar_arrive_remote(mbar_a, peer);
            }
            ltc_mbar_wait_par(mbar_a, parity);
            parity ^= 1u;
            // swap buffers
            const __half* tr = svR; svR = svW; svW = (__half*)tr;
            svWa = (svWa == svh1_a) ? svh0_a : svh1_a;
        }
        // svF now holds full fp32 v in BOTH CTAs; epilogue is redundant per CTA.

        // pulse: phi = v @ phase_W^T + phase_b
        {
            float ph = 0.f;
            const __half2* row = (const __half2*)((char*)sPh + d2 * (PH_PITCH*2));
            #pragma unroll
            for (int kk = 0; kk < 32; ++kk) {
                float2 wf = __half22float2(row[(k0 >> 1) + kk]);
                float2 v2 = *(const float2*)&svF[k0 + 2*kk];
                ph = fmaf(wf.x, v2.x, ph);
                ph = fmaf(wf.y, v2.y, ph);
            }
            red[tid] = ph;
        }
        __syncthreads();
        if (tid < 128) {
            float phi = red[tid] + red[tid + 128] + phb;
            float vv = svF[tid] + aamp * sinf(fmaf(omg, (float)t, phi));
            svF[tid] = vv;
            sgs[tid] = 0.5f + 0.5f * ltc_tanh_f32(0.5f * vv);
        }
        __syncthreads();
        // self-attend: v += beta * (sigmoid(v) @ sa_W^T)
        {
            float sa = 0.f;
            const __half2* row = (const __half2*)((char*)sSa + d2 * (PH_PITCH*2));
            #pragma unroll
            for (int kk = 0; kk < 32; ++kk) {
                float2 wf = __half22float2(row[(k0 >> 1) + kk]);
                float2 s2 = *(const float2*)&sgs[k0 + 2*kk];
                sa = fmaf(wf.x, s2.x, sa);
                sa = fmaf(wf.y, s2.y, sa);
            }
            red[tid] = sa;
        }
        __syncthreads();
        if (tid < 128) {
            float vv = fmaf(beta, red[tid] + red[tid + 128], svF[tid]);
            svF[tid] = vv;
            svh0[tid] = __float2half(vv);
            if ((tid >> 6) == (int)rank)
                out[(size_t)(b * Sdim + t) * Hdim + tid] = vv;
        }
        __syncthreads();
    }

    if (tid < 128 && (tid >> 6) == (int)rank)
        out[(size_t)Bdim * Sdim * Hdim + b * Hdim + tid] = svF[tid];
}

// ---------------- launch ----------------
extern "C" void kernel_launch(void* const* d_in, const int* in_sizes, int n_in,
                              void* d_out, int out_size)
{
    const float* x        = (const float*)d_in[0];
    const float* h0       = (const float*)d_in[1];
    const float* input_w  = (const float*)d_in[2];
    const float* input_b  = (const float*)d_in[3];
    const float* gleak    = (const float*)d_in[4];
    const float* vleak    = (const float*)d_in[5];
    const float* cm       = (const float*)d_in[6];
    const float* sigma    = (const float*)d_in[7];
    const float* mu       = (const float*)d_in[8];
    const float* w        = (const float*)d_in[9];
    const float* erev     = (const float*)d_in[10];
    const float* s_sigma  = (const float*)d_in[11];
    const float* s_mu     = (const float*)d_in[12];
    const float* s_w      = (const float*)d_in[13];
    const float* s_erev   = (const float*)d_in[14];
    const float* amplitude= (const float*)d_in[15];
    const float* omega    = (const float*)d_in[16];
    const float* phase_W  = (const float*)d_in[17];
    const float* phase_b  = (const float*)d_in[18];
    const float* alpha    = (const float*)d_in[19];
    const float* sa_W     = (const float*)d_in[20];
    const float* beta     = (const float*)d_in[21];
    float* out = (float*)d_out;

    ltc_pre1<<<64, 256>>>(sigma, mu, w, erev, s_sigma, s_mu, s_w, s_erev,
                          input_w, input_b, phase_W, sa_W);
    ltc_pre2<<<1, 128>>>(gleak, vleak, cm, w, erev, s_w, s_erev);

    cudaFuncSetAttribute(ltc_sensory, cudaFuncAttributeMaxDynamicSharedMemorySize, SEN_SMEM);
    ltc_sensory<<<148, 256, SEN_SMEM>>>(x);

    cudaFuncSetAttribute(ltc_scan, cudaFuncAttributeMaxDynamicSharedMemorySize, SCAN_SMEM);
    ltc_scan<<<Bdim * 2, 256, SCAN_SMEM>>>(h0, amplitude, omega, phase_b,
                                           alpha, beta, out);
}

// round 6
// speedup vs baseline: 2.4326x; 1.2193x over previous
#include <cuda_runtime.h>
#include <cuda_fp16.h>
#include <math.h>
#include <stdint.h>

#define Bdim 64
#define Sdim 256
#define Idim 128
#define Hdim 128
#define UNF  6
#define EPSV 1e-8f

// ---------------- device scratch ----------------
// pair-packed recurrent params: index e = p*128 + d, p = src/2 (0..63)
__device__ __half2 g_RP1h[64*Hdim];  // (0.5*sigma[2p,d], 0.5*sigma[2p+1,d])
__device__ __half2 g_RCh [64*Hdim];  // (-0.5*sigma*mu) pairs
__device__ float2  g_RWf [64*Hdim];  // (0.5*softplus(w)*erev) pairs, fp32
// pair-packed sensory params (fp16, same as R5)
__device__ __half2 g_SP1[64*Hdim];
__device__ __half2 g_SC [64*Hdim];
__device__ __half2 g_SW [64*Hdim];
// epilogue matvec weights, [d][k] row-major fp16
__device__ __half  g_Ph[Hdim*Hdim];
__device__ __half  g_Sa[Hdim*Hdim];
__device__ float   g_KN[Hdim];
__device__ float   g_KD[Hdim];
__device__ float   g_CmT[Hdim];
__device__ float2  g_Sen[Bdim*Sdim*Hdim];   // per-(b,t,d): (num_s, den_s)

static __device__ __forceinline__ float ltc_softplus(float x) {
    return fmaxf(x, 0.f) + log1pf(expf(-fabsf(x)));
}
static __device__ __forceinline__ float ltc_tanh_f32(float x) {
    float y; asm("tanh.approx.f32 %0, %1;" : "=f"(y) : "f"(x)); return y;
}
static __device__ __forceinline__ __half2 ltc_tanh_h2(__half2 x) {
    uint32_t xi = *reinterpret_cast<uint32_t*>(&x);
    uint32_t yi;
    asm("tanh.approx.f16x2 %0, %1;" : "=r"(yi) : "r"(xi));
    return *reinterpret_cast<__half2*>(&yi);
}

// ---------------- precompute ----------------
__global__ void ltc_pre1(const float* __restrict__ sigma, const float* __restrict__ mu,
                         const float* __restrict__ w,     const float* __restrict__ erev,
                         const float* __restrict__ s_sigma, const float* __restrict__ s_mu,
                         const float* __restrict__ s_w,   const float* __restrict__ s_erev,
                         const float* __restrict__ input_w, const float* __restrict__ input_b,
                         const float* __restrict__ phase_W, const float* __restrict__ sa_W)
{
    int e = blockIdx.x * blockDim.x + threadIdx.x;
    if (e >= Hdim * Hdim) return;
    // epilogue weights: identity layout [d][k]
    g_Ph[e] = __float2half(phase_W[e]);
    g_Sa[e] = __float2half(sa_W[e]);

    if (e < 64 * Hdim) {
        int p = e >> 7, d = e & 127;
        int s0 = 2 * p, s1 = 2 * p + 1;
        float sg0 = sigma[s0*Hdim+d], sg1 = sigma[s1*Hdim+d];
        g_RP1h[e] = __floats2half2_rn(0.5f*sg0, 0.5f*sg1);
        g_RCh [e] = __floats2half2_rn(-0.5f*sg0*mu[s0*Hdim+d], -0.5f*sg1*mu[s1*Hdim+d]);
        g_RWf [e] = make_float2(0.5f*ltc_softplus(w[s0*Hdim+d])*erev[s0*Hdim+d],
                                0.5f*ltc_softplus(w[s1*Hdim+d])*erev[s1*Hdim+d]);
        float ss0 = s_sigma[s0*Hdim+d], ss1 = s_sigma[s1*Hdim+d];
        g_SP1[e] = __floats2half2_rn(0.5f*ss0*input_w[s0], 0.5f*ss1*input_w[s1]);
        g_SC [e] = __floats2half2_rn(0.5f*ss0*(input_b[s0]-s_mu[s0*Hdim+d]),
                                     0.5f*ss1*(input_b[s1]-s_mu[s1*Hdim+d]));
        g_SW [e] = __floats2half2_rn(0.5f*ltc_softplus(s_w[s0*Hdim+d])*s_erev[s0*Hdim+d],
                                     0.5f*ltc_softplus(s_w[s1*Hdim+d])*s_erev[s1*Hdim+d]);
    }
}

__global__ void ltc_pre2(const float* __restrict__ gleak, const float* __restrict__ vleak,
                         const float* __restrict__ cm,
                         const float* __restrict__ w, const float* __restrict__ erev,
                         const float* __restrict__ s_w, const float* __restrict__ s_erev)
{
    int d = threadIdx.x;
    if (d >= Hdim) return;
    float Cn = 0.f, Cd = 0.f;
    for (int s = 0; s < Hdim; ++s) {
        float v = 0.5f * ltc_softplus(w[s*Hdim+d]) * erev[s*Hdim+d];
        Cn += v; Cd += fabsf(v);
    }
    for (int i = 0; i < Idim; ++i) {
        float v = 0.5f * ltc_softplus(s_w[i*Hdim+d]) * s_erev[i*Hdim+d];
        Cn += v; Cd += fabsf(v);
    }
    float gl  = ltc_softplus(gleak[d]);
    float cmt = ltc_softplus(cm[d]) * ((float)UNF / 1.0f);
    g_KN[d]  = gl * vleak[d] + Cn;
    g_KD[d]  = cmt + gl + Cd + EPSV;
    g_CmT[d] = cmt;
}

// ---------------- sensory precompute (parallel over all (b,t)) ----------------
// smem: sP1 32768 @0, sC 32768 @32768, sW 32768 @65536, sxh 256 @98304, red 2048 @98560
#define SEN_SMEM 100608

__global__ __launch_bounds__(256, 1)
void ltc_sensory(const float* __restrict__ x)
{
    extern __shared__ char smem[];
    __half2* sP1 = (__half2*)smem;
    __half2* sC  = (__half2*)(smem + 32768);
    __half2* sW  = (__half2*)(smem + 65536);
    __half2* sxh = (__half2*)(smem + 98304);
    float*   red = (float*)(smem + 98560);

    const int tid = threadIdx.x;
    for (int i = tid; i < 64*Hdim; i += 256) {
        sP1[i] = g_SP1[i]; sC[i] = g_SC[i]; sW[i] = g_SW[i];
    }
    __syncthreads();

    const int d  = tid & 127;
    const int p0 = (tid >> 7) * 32;

    for (int item = blockIdx.x; item < Bdim*Sdim; item += gridDim.x) {
        if (tid < 64) {
            float2 x2 = ((const float2*)(x + (size_t)item * Idim))[tid];
            sxh[tid] = __floats2half2_rn(x2.x, x2.y);
        }
        __syncthreads();
        float qn = 0.f, qd = 0.f;
        #pragma unroll
        for (int i = 0; i < 32; ++i) {
            int e = (p0 + i) * Hdim + d;
            __half2 arg = __hfma2(sP1[e], sxh[p0 + i], sC[e]);
            float2 th = __half22float2(ltc_tanh_h2(arg));
            float2 wf = __half22float2(sW[e]);
            qn = fmaf(wf.x, th.x, qn); qn = fmaf(wf.y, th.y, qn);
            qd = fmaf(fabsf(wf.x), th.x, qd); qd = fmaf(fabsf(wf.y), th.y, qd);
        }
        red[tid] = qn;
        red[256 + tid] = qd;
        __syncthreads();
        if (tid < 128)
            g_Sen[(size_t)item * Hdim + tid] = make_float2(red[tid] + red[tid + 128],
                                                           red[256 + tid] + red[384 + tid]);
        __syncthreads();
    }
}

// ---------------- scan kernel: 1 CTA per batch, 512 threads, params in regs ----
// smem:
//   0      sPh  half [128 rows, pitch 130] 33280
//   33280  sSa  half [128 rows, pitch 130] 33280 -> 66560
//   66560  svF  float[128]   512 -> 67072
//   67072  sgs  float[128]   512 -> 67584
//   67584  red  float[1024] 4096 -> 71680
#define SCAN_SMEM 71680
#define PH_PITCH 130

__global__ __launch_bounds__(512, 1)
void ltc_scan(const float* __restrict__ h0,
              const float* __restrict__ amplitude, const float* __restrict__ omega,
              const float* __restrict__ phase_b,
              const float* __restrict__ alpha_p, const float* __restrict__ beta_p,
              float* __restrict__ out)
{
    extern __shared__ char smem[];
    __half* sPh = (__half*)smem;
    __half* sSa = (__half*)(smem + 33280);
    float*  svF = (float*)(smem + 66560);
    float*  sgs = (float*)(smem + 67072);
    float*  red = (float*)(smem + 67584);

    const int tid = threadIdx.x;
    const int b   = blockIdx.x;
    const int d   = tid & 127;
    const int q   = tid >> 7;        // src-pair quarter 0..3
    const int p0  = q * 16;

    // ---- load recurrent params into REGISTERS (owned slice, constant all steps)
    __half2 rp1[16], rc[16];
    float2  rw[16];
    #pragma unroll
    for (int i = 0; i < 16; ++i) {
        int e = (p0 + i) * Hdim + d;
        rp1[i] = g_RP1h[e];
        rc[i]  = g_RCh[e];
        rw[i]  = g_RWf[e];
    }

    // ---- epilogue weights into padded smem rows (pitch 130 halfs)
    {
        const __half2* ph2 = (const __half2*)g_Ph;
        const __half2* sa2 = (const __half2*)g_Sa;
        #pragma unroll 2
        for (int i = tid; i < (Hdim*Hdim)/2; i += 512) {
            int dd = i >> 6, jj = i & 63;
            ((__half2*)((char*)sPh + dd * (PH_PITCH*2)))[jj] = ph2[i];
            ((__half2*)((char*)sSa + dd * (PH_PITCH*2)))[jj] = sa2[i];
        }
    }
    if (tid < 128) svF[tid] = h0[b * Hdim + tid];
    __syncthreads();

    const float alpha = *alpha_p;
    const float beta  = *beta_p;

    // per-dst constants (writers tid<128)
    float KN = 0.f, KD = 0.f, cmt = 0.f, aamp = 0.f, omg = 0.f, phb = 0.f, vreg = 0.f;
    if (tid < 128) {
        KN = g_KN[d]; KD = g_KD[d]; cmt = g_CmT[d];
        aamp = alpha * amplitude[d]; omg = omega[d]; phb = phase_b[d];
        vreg = svF[d];
    }

    const int k0 = q * 32;          // epilogue k quarter

    for (int t = 0; t < Sdim; ++t) {
        float N0 = 0.f, D0 = 0.f;
        if (tid < 128) {
            float2 sen = g_Sen[(size_t)(b * Sdim + t) * Hdim + d];
            N0 = KN + sen.x; D0 = KD + sen.y;
        }

        #pragma unroll 1
        for (int u = 0; u < UNF; ++u) {
            const float2* sv2 = (const float2*)svF;
            float qn = 0.f, qd = 0.f;
            #pragma unroll
            for (int i = 0; i < 16; ++i) {
                float2 v2 = sv2[p0 + i];                       // bcast LDS.64
                __half2 vh = __floats2half2_rn(v2.x, v2.y);
                __half2 arg = __hfma2(rp1[i], vh, rc[i]);
                float2 th = __half22float2(ltc_tanh_h2(arg));
                qn = fmaf(rw[i].x, th.x, qn);
                qn = fmaf(rw[i].y, th.y, qn);
                qd = fmaf(fabsf(rw[i].x), th.x, qd);
                qd = fmaf(fabsf(rw[i].y), th.y, qd);
            }
            red[tid] = qn;
            red[512 + tid] = qd;
            __syncthreads();
            if (tid < 128) {
                float num = N0 + red[d] + red[d+128] + red[d+256] + red[d+384];
                float den = D0 + red[512+d] + red[512+d+128] + red[512+d+256] + red[512+d+384];
                vreg = __fdividef(fmaf(cmt, vreg, num), den);
                svF[d] = vreg;
            }
            __syncthreads();
        }

        // ---- pulse: phi = v @ phase_W^T + phase_b  (k split over quarters)
        {
            float ph = 0.f;
            const __half2* row = (const __half2*)(sPh + d * PH_PITCH) + (k0 >> 1);
            const float2* sv2 = (const float2*)svF + (k0 >> 1);
            #pragma unroll
            for (int j = 0; j < 16; ++j) {
                float2 wf = __half22float2(row[j]);
                float2 v2 = sv2[j];
                ph = fmaf(wf.x, v2.x, ph);
                ph = fmaf(wf.y, v2.y, ph);
            }
            red[tid] = ph;
        }
        __syncthreads();
        if (tid < 128) {
            float phi = red[d] + red[d+128] + red[d+256] + red[d+384] + phb;
            vreg = fmaf(aamp, sinf(fmaf(omg, (float)t, phi)), vreg);
            svF[d] = vreg;
            sgs[d] = 0.5f + 0.5f * ltc_tanh_f32(0.5f * vreg);
        }
        __syncthreads();
        // ---- self-attend: v += beta * (sigmoid(v) @ sa_W^T)
        {
            float sa = 0.f;
            const __half2* row = (const __half2*)(sSa + d * PH_PITCH) + (k0 >> 1);
            const float2* sg2 = (const float2*)sgs + (k0 >> 1);
            #pragma unroll
            for (int j = 0; j < 16; ++j) {
                float2 wf = __half22float2(row[j]);
                float2 s2 = sg2[j];
                sa = fmaf(wf.x, s2.x, sa);
                sa = fmaf(wf.y, s2.y, sa);
            }
            red[tid] = sa;
        }
        __syncthreads();
        if (tid < 128) {
            vreg = fmaf(beta, red[d] + red[d+128] + red[d+256] + red[d+384], vreg);
            svF[d] = vreg;
            out[(size_t)(b * Sdim + t) * Hdim + d] = vreg;
        }
        __syncthreads();
    }

    if (tid < 128)
        out[(size_t)Bdim * Sdim * Hdim + b * Hdim + d] = vreg;
}

// ---------------- launch ----------------
extern "C" void kernel_launch(void* const* d_in, const int* in_sizes, int n_in,
                              void* d_out, int out_size)
{
    const float* x        = (const float*)d_in[0];
    const float* h0       = (const float*)d_in[1];
    const float* input_w  = (const float*)d_in[2];
    const float* input_b  = (const float*)d_in[3];
    const float* gleak    = (const float*)d_in[4];
    const float* vleak    = (const float*)d_in[5];
    const float* cm       = (const float*)d_in[6];
    const float* sigma    = (const float*)d_in[7];
    const float* mu       = (const float*)d_in[8];
    const float* w        = (const float*)d_in[9];
    const float* erev     = (const float*)d_in[10];
    const float* s_sigma  = (const float*)d_in[11];
    const float* s_mu     = (const float*)d_in[12];
    const float* s_w      = (const float*)d_in[13];
    const float* s_erev   = (const float*)d_in[14];
    const float* amplitude= (const float*)d_in[15];
    const float* omega    = (const float*)d_in[16];
    const float* phase_W  = (const float*)d_in[17];
    const float* phase_b  = (const float*)d_in[18];
    const float* alpha    = (const float*)d_in[19];
    const float* sa_W     = (const float*)d_in[20];
    const float* beta     = (const float*)d_in[21];
    float* out = (float*)d_out;

    ltc_pre1<<<64, 256>>>(sigma, mu, w, erev, s_sigma, s_mu, s_w, s_erev,
                          input_w, input_b, phase_W, sa_W);
    ltc_pre2<<<1, 128>>>(gleak, vleak, cm, w, erev, s_w, s_erev);

    cudaFuncSetAttribute(ltc_sensory, cudaFuncAttributeMaxDynamicSharedMemorySize, SEN_SMEM);
    ltc_sensory<<<148, 256, SEN_SMEM>>>(x);

    cudaFuncSetAttribute(ltc_scan, cudaFuncAttributeMaxDynamicSharedMemorySize, SCAN_SMEM);
    ltc_scan<<<Bdim, 512, SCAN_SMEM>>>(h0, amplitude, omega, phase_b,
                                       alpha, beta, out);
}